// round 14
// baseline (speedup 1.0000x reference)
#include <cuda_runtime.h>
#include <cuda_fp16.h>
#include <math.h>
#include <stdint.h>

#define N_NODES 50000
#define N_EDGES 800000
#define NFEAT   512
#define NHID    128
#define NCLASS  64

// Scratch (allocation-free)
__device__ uint16_t g_x16[(size_t)N_NODES * NFEAT];   // fp16(X)
__device__ uint16_t g_h0[(size_t)N_NODES * NHID];
__device__ uint16_t g_h1[(size_t)N_NODES * NHID];
__device__ uint16_t g_w1t_hi[NHID * NFEAT];   // W1^T hi fp16 [n][k]
__device__ uint16_t g_w1t_lo[NHID * NFEAT];   // W1^T lo fp16 [n][k]
__device__ uint16_t g_w2t_hi[NCLASS * NHID];  // W2^T hi fp16 [n][k]
__device__ uint16_t g_w2t_lo[NCLASS * NHID];  // W2^T lo fp16 [n][k]
__device__ int g_rowptr[N_NODES + 1];

// ---------------------------------------------------------------------------
// helpers
// ---------------------------------------------------------------------------
__device__ __forceinline__ uint32_t smem_u32(const void* p) {
    uint32_t a;
    asm("{ .reg .u64 t; cvta.to.shared.u64 t, %1; cvt.u32.u64 %0, t; }" : "=r"(a) : "l"(p));
    return a;
}
__device__ __forceinline__ uint32_t pack_f16x2(float lo, float hi) {
    uint32_t r;
    asm("cvt.rn.f16x2.f32 %0, %1, %2;" : "=r"(r) : "f"(hi), "f"(lo));
    return r;
}
__device__ __forceinline__ float f16_lo_f32(uint32_t p) {
    float f; asm("{ .reg .f16 h; mov.b32 {h, _}, %1; cvt.f32.f16 %0, h; }" : "=f"(f) : "r"(p));
    return f;
}
__device__ __forceinline__ float f16_hi_f32(uint32_t p) {
    float f; asm("{ .reg .f16 h; mov.b32 {_, h}, %1; cvt.f32.f16 %0, h; }" : "=f"(f) : "r"(p));
    return f;
}

__device__ __forceinline__ void mma_f16(float* d, const uint32_t* a,
                                        uint32_t b0, uint32_t b1) {
    asm("mma.sync.aligned.m16n8k16.row.col.f32.f16.f16.f32 "
        "{%0,%1,%2,%3}, {%4,%5,%6,%7}, {%8,%9}, {%0,%1,%2,%3};"
        : "+f"(d[0]), "+f"(d[1]), "+f"(d[2]), "+f"(d[3])
        : "r"(a[0]), "r"(a[1]), "r"(a[2]), "r"(a[3]), "r"(b0), "r"(b1));
}
#define LDSM4(r0, r1, r2, r3, addr) \
    asm volatile("ldmatrix.sync.aligned.m8n8.x4.shared.b16 {%0,%1,%2,%3}, [%4];" \
        : "=r"(r0), "=r"(r1), "=r"(r2), "=r"(r3) : "r"(addr))

__device__ __forceinline__ void cp_async16(uint32_t dst, const void* src) {
    asm volatile("cp.async.cg.shared.global [%0], [%1], 16;" :: "r"(dst), "l"(src));
}
#define CP_COMMIT() asm volatile("cp.async.commit_group;" ::: "memory")
#define CP_WAIT0()  asm volatile("cp.async.wait_group 0;" ::: "memory")
#define CP_WAIT1()  asm volatile("cp.async.wait_group 1;" ::: "memory")

// ---------------------------------------------------------------------------
// prep kernels
// ---------------------------------------------------------------------------
__global__ void conv_x_kernel(const float* __restrict__ x) {
    size_t i = ((size_t)blockIdx.x * 256 + threadIdx.x) * 8;
    if (i >= (size_t)N_NODES * NFEAT) return;
    float4 a = *(const float4*)(x + i);
    float4 b = *(const float4*)(x + i + 4);
    uint4 p;
    p.x = pack_f16x2(a.x, a.y);
    p.y = pack_f16x2(a.z, a.w);
    p.z = pack_f16x2(b.x, b.y);
    p.w = pack_f16x2(b.z, b.w);
    *(uint4*)(g_x16 + i) = p;
}

__global__ void prep_w1_kernel(const float* __restrict__ W1) {
    int idx = blockIdx.x * 256 + threadIdx.x;
    if (idx >= NHID * NFEAT / 2) return;
    int n = idx >> 8;
    int k2 = (idx & 255) * 2;
    float w0 = W1[(size_t)k2 * NHID + n];
    float w1 = W1[(size_t)(k2 + 1) * NHID + n];
    uint32_t ph = pack_f16x2(w0, w1);
    uint32_t pl = pack_f16x2(w0 - f16_lo_f32(ph), w1 - f16_hi_f32(ph));
    *(uint32_t*)&g_w1t_hi[n * NFEAT + k2] = ph;
    *(uint32_t*)&g_w1t_lo[n * NFEAT + k2] = pl;
}

__global__ void prep_w2_kernel(const float* __restrict__ W2) {
    int idx = blockIdx.x * 256 + threadIdx.x;
    if (idx >= NCLASS * NHID / 2) return;
    int n = idx >> 6;
    int k2 = (idx & 63) * 2;
    float w0 = W2[(size_t)k2 * NCLASS + n];
    float w1 = W2[(size_t)(k2 + 1) * NCLASS + n];
    uint32_t ph = pack_f16x2(w0, w1);
    uint32_t pl = pack_f16x2(w0 - f16_lo_f32(ph), w1 - f16_hi_f32(ph));
    *(uint32_t*)&g_w2t_hi[n * NHID + k2] = ph;
    *(uint32_t*)&g_w2t_lo[n * NHID + k2] = pl;
}

__global__ void rowptr_kernel(const int* __restrict__ rows) {
    int e = blockIdx.x * 256 + threadIdx.x;
    if (e >= N_EDGES) return;
    int r = rows[e];
    int rp = (e == 0) ? -1 : rows[e - 1];
    for (int q = rp + 1; q <= r; ++q) g_rowptr[q] = e;
    if (e == N_EDGES - 1)
        for (int q = r + 1; q <= N_NODES; ++q) g_rowptr[q] = N_EDGES;
}

// ---------------------------------------------------------------------------
// GEMM1: fp16 2-term, A pre-converted (no staging/conv), double-buffered.
// CTA 128x128, 512 threads, 16 warps (8M x 2N), warp tile 16x64, BK=32.
// SMEM: A 2x5120 + B(hi|lo) 2x10240 = 30720 elems = 61440 B -> 2 CTAs/SM.
// ---------------------------------------------------------------------------
#define LDA   40
#define ABUF(b) ((b) * 5120)
#define BBUF(b) (10240 + (b) * 10240)
#define SMEM_G1_BYTES (30720 * 2)   // 61440

__global__ __launch_bounds__(512, 2) void gemm1_mma_kernel(uint16_t* __restrict__ out)
{
    extern __shared__ uint16_t sm[];
    const uint32_t smb = smem_u32(sm);

    const int tid  = threadIdx.x;
    const int wid  = tid >> 5;        // 0..15
    const int lane = tid & 31;
    const int m0   = blockIdx.x * 128;
    const int wm = (wid >> 1) * 16;   // 0..112
    const int wn = (wid & 1) * 64;    // 0,64

    float acc[8][4];
#pragma unroll
    for (int j = 0; j < 8; j++)
#pragma unroll
        for (int q = 0; q < 4; q++) acc[j][q] = 0.f;

    // copy mapping: 4 threads per row, 8 halves (16 B) each
    const int arow = tid >> 2;        // 0..127
    const int aq   = tid & 3;         // 0..3
    int rg = m0 + arow;
    if (rg >= N_NODES) rg = N_NODES - 1;
    const uint16_t* xrow  = g_x16    + (size_t)rg * NFEAT + aq * 8;
    const uint16_t* bhrow = g_w1t_hi + (size_t)arow * NFEAT + aq * 8;
    const uint16_t* blrow = g_w1t_lo + (size_t)arow * NFEAT + aq * 8;
    const int dstA = arow * LDA + aq * 8;
    const int dstB = arow * LDA + aq * 8;

    const int lrow = (lane & 7) + ((lane >> 3) & 1) * 8;
    const int lkof = (lane >> 4) * 8;
    const uint32_t aRel = (uint32_t)(((wm + lrow) * LDA + lkof) * 2);
    const uint32_t bRel = (uint32_t)(((wn + lrow) * LDA + lkof) * 2);

#define COPY_AB(c, buf) do {                                                  \
        cp_async16(smb + (ABUF(buf) + dstA) * 2, xrow + (c) * 32);            \
        uint32_t dh = smb + (BBUF(buf) + dstB) * 2;                           \
        cp_async16(dh,            bhrow + (c) * 32);                          \
        cp_async16(dh + 5120 * 2, blrow + (c) * 32);                          \
        CP_COMMIT();                                                          \
    } while (0)

    COPY_AB(0, 0);
    COPY_AB(1, 1);

#pragma unroll 1
    for (int c = 0; c < 16; ++c) {
        if (c < 15) CP_WAIT1();
        else        CP_WAIT0();
        __syncthreads();

        const uint32_t aBase = smb + (uint32_t)(ABUF(c & 1) * 2) + aRel;
        const uint32_t bHi   = smb + (uint32_t)(BBUF(c & 1) * 2) + bRel;
        const uint32_t bLo   = bHi + 5120 * 2;
#pragma unroll
        for (int ks = 0; ks < 2; ++ks) {
            const uint32_t kb = ks * 32;
            uint32_t a0[4];
            LDSM4(a0[0], a0[1], a0[2], a0[3], aBase + kb);
#pragma unroll
            for (int ntp = 0; ntp < 4; ++ntp) {
                const uint32_t boff = (uint32_t)(ntp * 16 * LDA * 2) + kb;
                uint32_t bh[4], bl[4];
                LDSM4(bh[0], bh[1], bh[2], bh[3], bHi + boff);
                LDSM4(bl[0], bl[1], bl[2], bl[3], bLo + boff);
                float* c0 = acc[ntp * 2];
                float* c1 = acc[ntp * 2 + 1];
                mma_f16(c0, a0, bh[0], bh[2]);
                mma_f16(c1, a0, bh[1], bh[3]);
                mma_f16(c0, a0, bl[0], bl[2]);
                mma_f16(c1, a0, bl[1], bl[3]);
            }
        }
        __syncthreads();

        if (c < 14) COPY_AB(c + 2, c & 1);
    }

    // epilogue: fp16 output
    {
        int r0 = m0 + wm + (lane >> 2);
        int r1 = r0 + 8;
#pragma unroll
        for (int nt = 0; nt < 8; ++nt) {
            int cc = wn + nt * 8 + (lane & 3) * 2;
            if (r0 < N_NODES)
                *(uint32_t*)(out + (size_t)r0 * NHID + cc) =
                    pack_f16x2(acc[nt][0], acc[nt][1]);
            if (r1 < N_NODES)
                *(uint32_t*)(out + (size_t)r1 * NHID + cc) =
                    pack_f16x2(acc[nt][2], acc[nt][3]);
        }
    }
}

// ---------------------------------------------------------------------------
// SpMM: warp per row, row_ptr, 4-edge unroll, fp16 h. (kept)
// ---------------------------------------------------------------------------
template <bool RELU>
__global__ __launch_bounds__(256) void spmm_kernel(const int* __restrict__ cols,
                                                   const float* __restrict__ vals,
                                                   const uint16_t* __restrict__ hin,
                                                   const float* __restrict__ bias,
                                                   uint16_t* __restrict__ hout)
{
    const int gw   = (blockIdx.x * blockDim.x + threadIdx.x) >> 5;
    const int lane = threadIdx.x & 31;
    if (gw >= N_NODES) return;

    const int start = g_rowptr[gw];
    const int end   = g_rowptr[gw + 1];

    float ax = 0.f, ay = 0.f, az = 0.f, aw = 0.f;
    int e = start;
    for (; e + 4 <= end; e += 4) {
        int   c0 = cols[e],     c1 = cols[e + 1], c2 = cols[e + 2], c3 = cols[e + 3];
        float v0 = vals[e],     v1 = vals[e + 1], v2 = vals[e + 2], v3 = vals[e + 3];
        uint2 p0 = *(const uint2*)(hin + (size_t)c0 * NHID + lane * 4);
        uint2 p1 = *(const uint2*)(hin + (size_t)c1 * NHID + lane * 4);
        uint2 p2 = *(const uint2*)(hin + (size_t)c2 * NHID + lane * 4);
        uint2 p3 = *(const uint2*)(hin + (size_t)c3 * NHID + lane * 4);
        float2 f;
        f = __half22float2(*(__half2*)&p0.x); ax = fmaf(v0, f.x, ax); ay = fmaf(v0, f.y, ay);
        f = __half22float2(*(__half2*)&p0.y); az = fmaf(v0, f.x, az); aw = fmaf(v0, f.y, aw);
        f = __half22float2(*(__half2*)&p1.x); ax = fmaf(v1, f.x, ax); ay = fmaf(v1, f.y, ay);
        f = __half22float2(*(__half2*)&p1.y); az = fmaf(v1, f.x, az); aw = fmaf(v1, f.y, aw);
        f = __half22float2(*(__half2*)&p2.x); ax = fmaf(v2, f.x, ax); ay = fmaf(v2, f.y, ay);
        f = __half22float2(*(__half2*)&p2.y); az = fmaf(v2, f.x, az); aw = fmaf(v2, f.y, aw);
        f = __half22float2(*(__half2*)&p3.x); ax = fmaf(v3, f.x, ax); ay = fmaf(v3, f.y, ay);
        f = __half22float2(*(__half2*)&p3.y); az = fmaf(v3, f.x, az); aw = fmaf(v3, f.y, aw);
    }
    for (; e < end; ++e) {
        int   c0 = cols[e];
        float v0 = vals[e];
        uint2 p0 = *(const uint2*)(hin + (size_t)c0 * NHID + lane * 4);
        float2 f;
        f = __half22float2(*(__half2*)&p0.x); ax = fmaf(v0, f.x, ax); ay = fmaf(v0, f.y, ay);
        f = __half22float2(*(__half2*)&p0.y); az = fmaf(v0, f.x, az); aw = fmaf(v0, f.y, aw);
    }
    if (RELU) {
        float4 b = ((const float4*)bias)[lane];
        ax = fmaxf(ax + b.x, 0.f); ay = fmaxf(ay + b.y, 0.f);
        az = fmaxf(az + b.z, 0.f); aw = fmaxf(aw + b.w, 0.f);
    }
    uint2 st;
    st.x = pack_f16x2(ax, ay);
    st.y = pack_f16x2(az, aw);
    *(uint2*)(hout + (size_t)gw * NHID + lane * 4) = st;
}

// ---------------------------------------------------------------------------
// GEMM2: fp16 2-term + fused bias + log_softmax. (kept)
// ---------------------------------------------------------------------------
#define LDH 136
#define G2_A  0
#define G2_WH 8704
#define G2_WL 17408
#define SMEM_G2_BYTES (26112 * 2)   // 52224

__global__ __launch_bounds__(128) void gemm2_mma_kernel(const uint16_t* __restrict__ h,
                                                        const float* __restrict__ b2,
                                                        float* __restrict__ out)
{
    extern __shared__ uint16_t s2[];

    const int tid  = threadIdx.x;
    const int lane = tid & 31;
    const int wid  = tid >> 5;
    const int r0   = blockIdx.x * 64;

    const int row = tid >> 1, half = tid & 1;
    int rg = r0 + row;
    if (rg >= N_NODES) rg = N_NODES - 1;

    {
        const uint16_t* hp = h + (size_t)rg * NHID + half * 64;
        uint16_t* dp = s2 + G2_A + row * LDH + half * 64;
#pragma unroll
        for (int j = 0; j < 8; ++j)
            *(uint4*)(dp + j * 8) = *(const uint4*)(hp + j * 8);
    }
    {
        const int n = row;
        const uint16_t* wh = g_w2t_hi + n * NHID + half * 64;
        const uint16_t* wl = g_w2t_lo + n * NHID + half * 64;
        uint16_t* dh = s2 + G2_WH + n * LDH + half * 64;
        uint16_t* dl = s2 + G2_WL + n * LDH + half * 64;
#pragma unroll
        for (int j = 0; j < 8; ++j) {
            *(uint4*)(dh + j * 8) = *(const uint4*)(wh + j * 8);
            *(uint4*)(dl + j * 8) = *(const uint4*)(wl + j * 8);
        }
    }
    __syncthreads();

    float acc[8][4];
#pragma unroll
    for (int nt = 0; nt < 8; ++nt)
#pragma unroll
        for (int q = 0; q < 4; ++q) acc[nt][q] = 0.f;

    const int wr = wid * 16;
#pragma unroll
    for (int ks = 0; ks < 8; ++ks) {
        const int kk = ks * 16;
        const int r  = wr + (lane >> 2);
        const int cc = kk + (lane & 3) * 2;
        uint32_t a[4];
        a[0] = *(const uint32_t*)(s2 + G2_A + r * LDH + cc);
        a[1] = *(const uint32_t*)(s2 + G2_A + (r + 8) * LDH + cc);
        a[2] = *(const uint32_t*)(s2 + G2_A + r * LDH + cc + 8);
        a[3] = *(const uint32_t*)(s2 + G2_A + (r + 8) * LDH + cc + 8);
#pragma unroll
        for (int nt = 0; nt < 8; ++nt) {
            int n  = nt * 8 + (lane >> 2);
            int kq = kk + (lane & 3) * 2;
            uint32_t bh0 = *(const uint32_t*)(s2 + G2_WH + n * LDH + kq);
            uint32_t bh1 = *(const uint32_t*)(s2 + G2_WH + n * LDH + kq + 8);
            uint32_t bl0 = *(const uint32_t*)(s2 + G2_WL + n * LDH + kq);
            uint32_t bl1 = *(const uint32_t*)(s2 + G2_WL + n * LDH + kq + 8);
            mma_f16(acc[nt], a, bh0, bh1);
            mma_f16(acc[nt], a, bl0, bl1);
        }
    }

#pragma unroll
    for (int nt = 0; nt < 8; ++nt) {
        int c = nt * 8 + (lane & 3) * 2;
        float bb0 = b2[c], bb1 = b2[c + 1];
        acc[nt][0] += bb0; acc[nt][1] += bb1;
        acc[nt][2] += bb0; acc[nt][3] += bb1;
    }

    float m0 = -1e30f, m1 = -1e30f;
#pragma unroll
    for (int nt = 0; nt < 8; ++nt) {
        m0 = fmaxf(m0, fmaxf(acc[nt][0], acc[nt][1]));
        m1 = fmaxf(m1, fmaxf(acc[nt][2], acc[nt][3]));
    }
    m0 = fmaxf(m0, __shfl_xor_sync(0xffffffffu, m0, 1));
    m0 = fmaxf(m0, __shfl_xor_sync(0xffffffffu, m0, 2));
    m1 = fmaxf(m1, __shfl_xor_sync(0xffffffffu, m1, 1));
    m1 = fmaxf(m1, __shfl_xor_sync(0xffffffffu, m1, 2));

    float s0 = 0.f, s1 = 0.f;
#pragma unroll
    for (int nt = 0; nt < 8; ++nt) {
        s0 += expf(acc[nt][0] - m0) + expf(acc[nt][1] - m0);
        s1 += expf(acc[nt][2] - m1) + expf(acc[nt][3] - m1);
    }
    s0 += __shfl_xor_sync(0xffffffffu, s0, 1);
    s0 += __shfl_xor_sync(0xffffffffu, s0, 2);
    s1 += __shfl_xor_sync(0xffffffffu, s1, 1);
    s1 += __shfl_xor_sync(0xffffffffu, s1, 2);
    const float lse0 = m0 + logf(s0);
    const float lse1 = m1 + logf(s1);

    const int row0 = r0 + wr + (lane >> 2);
    const int row1 = row0 + 8;
#pragma unroll
    for (int nt = 0; nt < 8; ++nt) {
        int c = nt * 8 + (lane & 3) * 2;
        if (row0 < N_NODES)
            *(float2*)(out + (size_t)row0 * NCLASS + c) =
                make_float2(acc[nt][0] - lse0, acc[nt][1] - lse0);
        if (row1 < N_NODES)
            *(float2*)(out + (size_t)row1 * NCLASS + c) =
                make_float2(acc[nt][2] - lse1, acc[nt][3] - lse1);
    }
}

// ---------------------------------------------------------------------------
extern "C" void kernel_launch(void* const* d_in, const int* in_sizes, int n_in,
                              void* d_out, int out_size)
{
    const float* x    = (const float*)d_in[0];
    const int*   rows = (const int*)  d_in[1];
    const int*   cols = (const int*)  d_in[2];
    const float* vals = (const float*)d_in[3];
    const float* W1   = (const float*)d_in[4];
    const float* b1   = (const float*)d_in[5];
    const float* W2   = (const float*)d_in[6];
    const float* b2   = (const float*)d_in[7];
    float* out = (float*)d_out;

    uint16_t *h0, *h1;
    cudaGetSymbolAddress((void**)&h0, g_h0);
    cudaGetSymbolAddress((void**)&h1, g_h1);

    cudaFuncSetAttribute(gemm1_mma_kernel, cudaFuncAttributeMaxDynamicSharedMemorySize, SMEM_G1_BYTES);
    cudaFuncSetAttribute(gemm2_mma_kernel, cudaFuncAttributeMaxDynamicSharedMemorySize, SMEM_G2_BYTES);

    // 0) prep: X -> fp16 (streaming), W1^T/W2^T hi-lo, row_ptr
    conv_x_kernel<<<(N_NODES * NFEAT / 8 + 255) / 256, 256>>>(x);
    prep_w1_kernel<<<(NHID * NFEAT / 2 + 255) / 256, 256>>>(W1);
    prep_w2_kernel<<<(NCLASS * NHID / 2 + 255) / 256, 256>>>(W2);
    rowptr_kernel<<<(N_EDGES + 255) / 256, 256>>>(rows);

    // 1) h0 = X16 @ W1  (all-fp16 cp.async, no staging)
    gemm1_mma_kernel<<<(N_NODES + 127) / 128, 512, SMEM_G1_BYTES>>>(h0);

    // 2) h1 = relu(A @ h0 + b1)
    const int spmm_blocks = (N_NODES * 32 + 255) / 256;
    spmm_kernel<true><<<spmm_blocks, 256>>>(cols, vals, h0, b1, h1);

    // 3) h0 <- A @ h1
    spmm_kernel<false><<<spmm_blocks, 256>>>(cols, vals, h1, b1, h0);

    // 4) out = logsoftmax(h0 @ W2 + b2)
    gemm2_mma_kernel<<<(N_NODES + 63) / 64, 128, SMEM_G2_BYTES>>>(h0, b2, out);
}

// round 15
// speedup vs baseline: 1.0763x; 1.0763x over previous
#include <cuda_runtime.h>
#include <cuda_fp16.h>
#include <math.h>
#include <stdint.h>

#define N_NODES 50000
#define N_EDGES 800000
#define NFEAT   512
#define NHID    128
#define NCLASS  64

// Scratch (allocation-free) — h0/h1 fp16
__device__ uint16_t g_h0[(size_t)N_NODES * NHID];
__device__ uint16_t g_h1[(size_t)N_NODES * NHID];
__device__ uint16_t g_w1t_hi[NHID * NFEAT];   // W1^T hi fp16 [n][k]
__device__ uint16_t g_w1t_lo[NHID * NFEAT];   // W1^T lo fp16 [n][k]
__device__ uint16_t g_w2t_hi[NCLASS * NHID];  // W2^T hi fp16 [n][k]
__device__ uint16_t g_w2t_lo[NCLASS * NHID];  // W2^T lo fp16 [n][k]
__device__ int g_rowptr[N_NODES + 1];

// ---------------------------------------------------------------------------
// helpers
// ---------------------------------------------------------------------------
__device__ __forceinline__ uint32_t smem_u32(const void* p) {
    uint32_t a;
    asm("{ .reg .u64 t; cvta.to.shared.u64 t, %1; cvt.u32.u64 %0, t; }" : "=r"(a) : "l"(p));
    return a;
}
__device__ __forceinline__ uint32_t pack_f16x2(float lo, float hi) {
    uint32_t r;
    asm("cvt.rn.f16x2.f32 %0, %1, %2;" : "=r"(r) : "f"(hi), "f"(lo));
    return r;
}
__device__ __forceinline__ float f16_lo_f32(uint32_t p) {
    float f; asm("{ .reg .f16 h; mov.b32 {h, _}, %1; cvt.f32.f16 %0, h; }" : "=f"(f) : "r"(p));
    return f;
}
__device__ __forceinline__ float f16_hi_f32(uint32_t p) {
    float f; asm("{ .reg .f16 h; mov.b32 {_, h}, %1; cvt.f32.f16 %0, h; }" : "=f"(f) : "r"(p));
    return f;
}

__device__ __forceinline__ void mma_f16(float* d, const uint32_t* a,
                                        uint32_t b0, uint32_t b1) {
    asm("mma.sync.aligned.m16n8k16.row.col.f32.f16.f16.f32 "
        "{%0,%1,%2,%3}, {%4,%5,%6,%7}, {%8,%9}, {%0,%1,%2,%3};"
        : "+f"(d[0]), "+f"(d[1]), "+f"(d[2]), "+f"(d[3])
        : "r"(a[0]), "r"(a[1]), "r"(a[2]), "r"(a[3]), "r"(b0), "r"(b1));
}
#define LDSM4(r0, r1, r2, r3, addr) \
    asm volatile("ldmatrix.sync.aligned.m8n8.x4.shared.b16 {%0,%1,%2,%3}, [%4];" \
        : "=r"(r0), "=r"(r1), "=r"(r2), "=r"(r3) : "r"(addr))

__device__ __forceinline__ void cp_async16(uint32_t dst, const void* src) {
    asm volatile("cp.async.cg.shared.global [%0], [%1], 16;" :: "r"(dst), "l"(src));
}
#define CP_COMMIT() asm volatile("cp.async.commit_group;" ::: "memory")
#define CP_WAIT0()  asm volatile("cp.async.wait_group 0;" ::: "memory")
#define CP_WAIT2()  asm volatile("cp.async.wait_group 2;" ::: "memory")
#define CP_WAIT3()  asm volatile("cp.async.wait_group 3;" ::: "memory")

// ---------------------------------------------------------------------------
// merged prep kernel: [0,128) W1, [128,144) W2, [144, 144+3125) rowptr
// ---------------------------------------------------------------------------
#define PREP_W1_BLOCKS 128
#define PREP_W2_BLOCKS 16
#define PREP_RP_BLOCKS ((N_EDGES + 255) / 256)
#define PREP_BLOCKS (PREP_W1_BLOCKS + PREP_W2_BLOCKS + PREP_RP_BLOCKS)

__global__ void prep_all_kernel(const float* __restrict__ W1,
                                const float* __restrict__ W2,
                                const int* __restrict__ rows)
{
    const int b = blockIdx.x;
    if (b < PREP_W1_BLOCKS) {
        int idx = b * 256 + threadIdx.x;
        if (idx >= NHID * NFEAT / 2) return;
        int n = idx >> 8;
        int k2 = (idx & 255) * 2;
        float w0 = W1[(size_t)k2 * NHID + n];
        float w1 = W1[(size_t)(k2 + 1) * NHID + n];
        uint32_t ph = pack_f16x2(w0, w1);
        uint32_t pl = pack_f16x2(w0 - f16_lo_f32(ph), w1 - f16_hi_f32(ph));
        *(uint32_t*)&g_w1t_hi[n * NFEAT + k2] = ph;
        *(uint32_t*)&g_w1t_lo[n * NFEAT + k2] = pl;
    } else if (b < PREP_W1_BLOCKS + PREP_W2_BLOCKS) {
        int idx = (b - PREP_W1_BLOCKS) * 256 + threadIdx.x;
        if (idx >= NCLASS * NHID / 2) return;
        int n = idx >> 6;
        int k2 = (idx & 63) * 2;
        float w0 = W2[(size_t)k2 * NCLASS + n];
        float w1 = W2[(size_t)(k2 + 1) * NCLASS + n];
        uint32_t ph = pack_f16x2(w0, w1);
        uint32_t pl = pack_f16x2(w0 - f16_lo_f32(ph), w1 - f16_hi_f32(ph));
        *(uint32_t*)&g_w2t_hi[n * NHID + k2] = ph;
        *(uint32_t*)&g_w2t_lo[n * NHID + k2] = pl;
    } else {
        int e = (b - PREP_W1_BLOCKS - PREP_W2_BLOCKS) * 256 + threadIdx.x;
        if (e >= N_EDGES) return;
        int r = rows[e];
        int rp = (e == 0) ? -1 : rows[e - 1];
        for (int q = rp + 1; q <= r; ++q) g_rowptr[q] = e;
        if (e == N_EDGES - 1)
            for (int q = r + 1; q <= N_NODES; ++q) g_rowptr[q] = N_EDGES;
    }
}

// ---------------------------------------------------------------------------
// GEMM1: fp16 2-term, depth-2 async pipeline, ldmatrix, 512 threads.
// CTA 128x128, 16 warps (8M x 2N), warp tile 16x64, BK=32.  (R13, kept)
// ---------------------------------------------------------------------------
#define LDA   40
#define AF16  0
#define BBUF(b) (5120 + (b) * 10240)
#define FP16_ELEMS 25600
#define LDAF  36
#define STAGF 4608
#define SMEM_G1_BYTES (FP16_ELEMS * 2 + 3 * STAGF * 4)   // 106496

__global__ __launch_bounds__(512, 2) void gemm1_mma_kernel(const float* __restrict__ x,
                                                           uint16_t* __restrict__ out)
{
    extern __shared__ uint16_t sm[];
    float* stag = (float*)(sm + FP16_ELEMS);
    const uint32_t smb = smem_u32(sm);
    const uint32_t stb = smem_u32(stag);

    const int tid  = threadIdx.x;
    const int wid  = tid >> 5;        // 0..15
    const int lane = tid & 31;
    const int m0   = blockIdx.x * 128;
    const int wm = (wid >> 1) * 16;   // 0..112
    const int wn = (wid & 1) * 64;    // 0,64

    float acc[8][4];
#pragma unroll
    for (int j = 0; j < 8; j++)
#pragma unroll
        for (int q = 0; q < 4; q++) acc[j][q] = 0.f;

    const int arow = tid >> 2;        // 0..127
    const int aq   = tid & 3;         // 0..3
    int rg = m0 + arow;
    if (rg >= N_NODES) rg = N_NODES - 1;
    const float* xrow = x + (size_t)rg * NFEAT + aq * 8;
    const uint16_t* bhrow = g_w1t_hi + (size_t)arow * NFEAT + aq * 8;
    const uint16_t* blrow = g_w1t_lo + (size_t)arow * NFEAT + aq * 8;
    const int stA  = arow * LDAF + aq * 8;
    const int dstA = AF16 + arow * LDA + aq * 8;
    const int dstB = arow * LDA + aq * 8;

    const int lrow = (lane & 7) + ((lane >> 3) & 1) * 8;
    const int lkof = (lane >> 4) * 8;
    const uint32_t aAddr0 = smb + (uint32_t)((AF16 + (wm + lrow) * LDA + lkof) * 2);
    const uint32_t bRel   = (uint32_t)(((wn + lrow) * LDA + lkof) * 2);

#define COPY_A(c, st) do {                                                    \
        uint32_t da = stb + ((st) * STAGF + stA) * 4;                         \
        cp_async16(da,      xrow + (c) * 32);                                 \
        cp_async16(da + 16, xrow + (c) * 32 + 4);                             \
        CP_COMMIT();                                                          \
    } while (0)

#define COPY_B(c, buf) do {                                                   \
        uint32_t dh = smb + (BBUF(buf) + dstB) * 2;                           \
        uint32_t dl = dh + 5120 * 2;                                          \
        cp_async16(dh, bhrow + (c) * 32);                                     \
        cp_async16(dl, blrow + (c) * 32);                                     \
        CP_COMMIT();                                                          \
    } while (0)

#define CONV_A(st) do {                                                       \
        const float* sf = stag + (st) * STAGF + stA;                          \
        float4 v0 = *(const float4*)(sf);                                     \
        float4 v1 = *(const float4*)(sf + 4);                                 \
        uint32_t H[4];                                                        \
        H[0] = pack_f16x2(v0.x, v0.y); H[1] = pack_f16x2(v0.z, v0.w);         \
        H[2] = pack_f16x2(v1.x, v1.y); H[3] = pack_f16x2(v1.z, v1.w);         \
        *(uint4*)(sm + dstA) = *(uint4*)&H[0];                                \
    } while (0)

    COPY_A(0, 0);
    COPY_B(0, 0);
    COPY_A(1, 1);
    COPY_B(1, 1);

#pragma unroll 1
    for (int c = 0; c < 16; ++c) {
        if (c < 14) COPY_A(c + 2, (c + 2) % 3);

        if (c < 14)       CP_WAIT3();
        else if (c == 14) CP_WAIT2();
        else              CP_WAIT0();

        CONV_A(c % 3);
        __syncthreads();

        const uint32_t bHi = smb + (uint32_t)(BBUF(c & 1) * 2) + bRel;
        const uint32_t bLo = bHi + 5120 * 2;
#pragma unroll
        for (int ks = 0; ks < 2; ++ks) {
            const uint32_t kb = ks * 32;
            uint32_t a0[4];
            LDSM4(a0[0], a0[1], a0[2], a0[3], aAddr0 + kb);
#pragma unroll
            for (int ntp = 0; ntp < 4; ++ntp) {
                const uint32_t boff = (uint32_t)(ntp * 16 * LDA * 2) + kb;
                uint32_t bh[4], bl[4];
                LDSM4(bh[0], bh[1], bh[2], bh[3], bHi + boff);
                LDSM4(bl[0], bl[1], bl[2], bl[3], bLo + boff);
                float* c0 = acc[ntp * 2];
                float* c1 = acc[ntp * 2 + 1];
                mma_f16(c0, a0, bh[0], bh[2]);
                mma_f16(c1, a0, bh[1], bh[3]);
                mma_f16(c0, a0, bl[0], bl[2]);
                mma_f16(c1, a0, bl[1], bl[3]);
            }
        }
        __syncthreads();

        if (c < 14) COPY_B(c + 2, c & 1);
    }

    // epilogue: fp16 output
    {
        int r0 = m0 + wm + (lane >> 2);
        int r1 = r0 + 8;
#pragma unroll
        for (int nt = 0; nt < 8; ++nt) {
            int cc = wn + nt * 8 + (lane & 3) * 2;
            if (r0 < N_NODES)
                *(uint32_t*)(out + (size_t)r0 * NHID + cc) =
                    pack_f16x2(acc[nt][0], acc[nt][1]);
            if (r1 < N_NODES)
                *(uint32_t*)(out + (size_t)r1 * NHID + cc) =
                    pack_f16x2(acc[nt][2], acc[nt][3]);
        }
    }
}

// ---------------------------------------------------------------------------
// SpMM: warp per row; half-warp per edge (lane gathers uint4 = 8 fp16),
// 2 edges in flight per step + 2-step unroll; shfl_xor(16) combine.
// ---------------------------------------------------------------------------
template <bool RELU>
__global__ __launch_bounds__(256) void spmm_kernel(const int* __restrict__ cols,
                                                   const float* __restrict__ vals,
                                                   const uint16_t* __restrict__ hin,
                                                   const float* __restrict__ bias,
                                                   uint16_t* __restrict__ hout)
{
    const int gw   = (blockIdx.x * blockDim.x + threadIdx.x) >> 5;
    const int lane = threadIdx.x & 31;
    if (gw >= N_NODES) return;

    const int half = lane >> 4;      // 0/1: which edge of the pair
    const int sl   = lane & 15;      // feature slot: 8 features each

    const int start = g_rowptr[gw];
    const int end   = g_rowptr[gw + 1];

    float a0 = 0.f, a1 = 0.f, a2 = 0.f, a3 = 0.f;
    float a4 = 0.f, a5 = 0.f, a6 = 0.f, a7 = 0.f;

#define SPMM_EDGE(e) do {                                                     \
        int   cc = cols[e];                                                   \
        float vv = vals[e];                                                   \
        uint4 p = *(const uint4*)(hin + (size_t)cc * NHID + sl * 8);          \
        float2 f;                                                             \
        f = __half22float2(*(__half2*)&p.x); a0 = fmaf(vv, f.x, a0); a1 = fmaf(vv, f.y, a1); \
        f = __half22float2(*(__half2*)&p.y); a2 = fmaf(vv, f.x, a2); a3 = fmaf(vv, f.y, a3); \
        f = __half22float2(*(__half2*)&p.z); a4 = fmaf(vv, f.x, a4); a5 = fmaf(vv, f.y, a5); \
        f = __half22float2(*(__half2*)&p.w); a6 = fmaf(vv, f.x, a6); a7 = fmaf(vv, f.y, a7); \
    } while (0)

    int e = start + half;
    for (; e + 2 < end; e += 4) {     // this half-warp handles e and e+2
        SPMM_EDGE(e);
        SPMM_EDGE(e + 2);
    }
    if (e < end) SPMM_EDGE(e);

    // combine the two half-warps (features identical across halves)
    a0 += __shfl_xor_sync(0xffffffffu, a0, 16);
    a1 += __shfl_xor_sync(0xffffffffu, a1, 16);
    a2 += __shfl_xor_sync(0xffffffffu, a2, 16);
    a3 += __shfl_xor_sync(0xffffffffu, a3, 16);
    a4 += __shfl_xor_sync(0xffffffffu, a4, 16);
    a5 += __shfl_xor_sync(0xffffffffu, a5, 16);
    a6 += __shfl_xor_sync(0xffffffffu, a6, 16);
    a7 += __shfl_xor_sync(0xffffffffu, a7, 16);

    if (half == 0) {
        if (RELU) {
            float4 b0 = ((const float4*)bias)[sl * 2];
            float4 b1 = ((const float4*)bias)[sl * 2 + 1];
            a0 = fmaxf(a0 + b0.x, 0.f); a1 = fmaxf(a1 + b0.y, 0.f);
            a2 = fmaxf(a2 + b0.z, 0.f); a3 = fmaxf(a3 + b0.w, 0.f);
            a4 = fmaxf(a4 + b1.x, 0.f); a5 = fmaxf(a5 + b1.y, 0.f);
            a6 = fmaxf(a6 + b1.z, 0.f); a7 = fmaxf(a7 + b1.w, 0.f);
        }
        uint4 st;
        st.x = pack_f16x2(a0, a1);
        st.y = pack_f16x2(a2, a3);
        st.z = pack_f16x2(a4, a5);
        st.w = pack_f16x2(a6, a7);
        *(uint4*)(hout + (size_t)gw * NHID + sl * 8) = st;
    }
}

// ---------------------------------------------------------------------------
// GEMM2: fp16 2-term + fused bias + log_softmax. (R12/R13, kept)
// ---------------------------------------------------------------------------
#define LDH 136
#define G2_A  0
#define G2_WH 8704
#define G2_WL 17408
#define SMEM_G2_BYTES (26112 * 2)   // 52224

__global__ __launch_bounds__(128) void gemm2_mma_kernel(const uint16_t* __restrict__ h,
                                                        const float* __restrict__ b2,
                                                        float* __restrict__ out)
{
    extern __shared__ uint16_t s2[];

    const int tid  = threadIdx.x;
    const int lane = tid & 31;
    const int wid  = tid >> 5;
    const int r0   = blockIdx.x * 64;

    const int row = tid >> 1, half = tid & 1;
    int rg = r0 + row;
    if (rg >= N_NODES) rg = N_NODES - 1;

    {
        const uint16_t* hp = h + (size_t)rg * NHID + half * 64;
        uint16_t* dp = s2 + G2_A + row * LDH + half * 64;
#pragma unroll
        for (int j = 0; j < 8; ++j)
            *(uint4*)(dp + j * 8) = *(const uint4*)(hp + j * 8);
    }
    {
        const int n = row;
        const uint16_t* wh = g_w2t_hi + n * NHID + half * 64;
        const uint16_t* wl = g_w2t_lo + n * NHID + half * 64;
        uint16_t* dh = s2 + G2_WH + n * LDH + half * 64;
        uint16_t* dl = s2 + G2_WL + n * LDH + half * 64;
#pragma unroll
        for (int j = 0; j < 8; ++j) {
            *(uint4*)(dh + j * 8) = *(const uint4*)(wh + j * 8);
            *(uint4*)(dl + j * 8) = *(const uint4*)(wl + j * 8);
        }
    }
    __syncthreads();

    float acc[8][4];
#pragma unroll
    for (int nt = 0; nt < 8; ++nt)
#pragma unroll
        for (int q = 0; q < 4; ++q) acc[nt][q] = 0.f;

    const int wr = wid * 16;
#pragma unroll
    for (int ks = 0; ks < 8; ++ks) {
        const int kk = ks * 16;
        const int r  = wr + (lane >> 2);
        const int cc = kk + (lane & 3) * 2;
        uint32_t a[4];
        a[0] = *(const uint32_t*)(s2 + G2_A + r * LDH + cc);
        a[1] = *(const uint32_t*)(s2 + G2_A + (r + 8) * LDH + cc);
        a[2] = *(const uint32_t*)(s2 + G2_A + r * LDH + cc + 8);
        a[3] = *(const uint32_t*)(s2 + G2_A + (r + 8) * LDH + cc + 8);
#pragma unroll
        for (int nt = 0; nt < 8; ++nt) {
            int n  = nt * 8 + (lane >> 2);
            int kq = kk + (lane & 3) * 2;
            uint32_t bh0 = *(const uint32_t*)(s2 + G2_WH + n * LDH + kq);
            uint32_t bh1 = *(const uint32_t*)(s2 + G2_WH + n * LDH + kq + 8);
            uint32_t bl0 = *(const uint32_t*)(s2 + G2_WL + n * LDH + kq);
            uint32_t bl1 = *(const uint32_t*)(s2 + G2_WL + n * LDH + kq + 8);
            mma_f16(acc[nt], a, bh0, bh1);
            mma_f16(acc[nt], a, bl0, bl1);
        }
    }

#pragma unroll
    for (int nt = 0; nt < 8; ++nt) {
        int c = nt * 8 + (lane & 3) * 2;
        float bb0 = b2[c], bb1 = b2[c + 1];
        acc[nt][0] += bb0; acc[nt][1] += bb1;
        acc[nt][2] += bb0; acc[nt][3] += bb1;
    }

    float m0 = -1e30f, m1 = -1e30f;
#pragma unroll
    for (int nt = 0; nt < 8; ++nt) {
        m0 = fmaxf(m0, fmaxf(acc[nt][0], acc[nt][1]));
        m1 = fmaxf(m1, fmaxf(acc[nt][2], acc[nt][3]));
    }
    m0 = fmaxf(m0, __shfl_xor_sync(0xffffffffu, m0, 1));
    m0 = fmaxf(m0, __shfl_xor_sync(0xffffffffu, m0, 2));
    m1 = fmaxf(m1, __shfl_xor_sync(0xffffffffu, m1, 1));
    m1 = fmaxf(m1, __shfl_xor_sync(0xffffffffu, m1, 2));

    float s0 = 0.f, s1 = 0.f;
#pragma unroll
    for (int nt = 0; nt < 8; ++nt) {
        s0 += expf(acc[nt][0] - m0) + expf(acc[nt][1] - m0);
        s1 += expf(acc[nt][2] - m1) + expf(acc[nt][3] - m1);
    }
    s0 += __shfl_xor_sync(0xffffffffu, s0, 1);
    s0 += __shfl_xor_sync(0xffffffffu, s0, 2);
    s1 += __shfl_xor_sync(0xffffffffu, s1, 1);
    s1 += __shfl_xor_sync(0xffffffffu, s1, 2);
    const float lse0 = m0 + logf(s0);
    const float lse1 = m1 + logf(s1);

    const int row0 = r0 + wr + (lane >> 2);
    const int row1 = row0 + 8;
#pragma unroll
    for (int nt = 0; nt < 8; ++nt) {
        int c = nt * 8 + (lane & 3) * 2;
        if (row0 < N_NODES)
            *(float2*)(out + (size_t)row0 * NCLASS + c) =
                make_float2(acc[nt][0] - lse0, acc[nt][1] - lse0);
        if (row1 < N_NODES)
            *(float2*)(out + (size_t)row1 * NCLASS + c) =
                make_float2(acc[nt][2] - lse1, acc[nt][3] - lse1);
    }
}

// ---------------------------------------------------------------------------
extern "C" void kernel_launch(void* const* d_in, const int* in_sizes, int n_in,
                              void* d_out, int out_size)
{
    const float* x    = (const float*)d_in[0];
    const int*   rows = (const int*)  d_in[1];
    const int*   cols = (const int*)  d_in[2];
    const float* vals = (const float*)d_in[3];
    const float* W1   = (const float*)d_in[4];
    const float* b1   = (const float*)d_in[5];
    const float* W2   = (const float*)d_in[6];
    const float* b2   = (const float*)d_in[7];
    float* out = (float*)d_out;

    uint16_t *h0, *h1;
    cudaGetSymbolAddress((void**)&h0, g_h0);
    cudaGetSymbolAddress((void**)&h1, g_h1);

    cudaFuncSetAttribute(gemm1_mma_kernel, cudaFuncAttributeMaxDynamicSharedMemorySize, SMEM_G1_BYTES);
    cudaFuncSetAttribute(gemm2_mma_kernel, cudaFuncAttributeMaxDynamicSharedMemorySize, SMEM_G2_BYTES);

    // 0) merged prep: W1^T, W2^T hi/lo + row_ptr in one launch
    prep_all_kernel<<<PREP_BLOCKS, 256>>>(W1, W2, rows);

    // 1) h0 = X @ W1  (R13 fused pipeline)
    gemm1_mma_kernel<<<(N_NODES + 127) / 128, 512, SMEM_G1_BYTES>>>(x, h0);

    // 2) h1 = relu(A @ h0 + b1)
    const int spmm_blocks = (N_NODES * 32 + 255) / 256;
    spmm_kernel<true><<<spmm_blocks, 256>>>(cols, vals, h0, b1, h1);

    // 3) h0 <- A @ h1
    spmm_kernel<false><<<spmm_blocks, 256>>>(cols, vals, h1, b1, h0);

    // 4) out = logsoftmax(h0 @ W2 + b2)
    gemm2_mma_kernel<<<(N_NODES + 63) / 64, 128, SMEM_G2_BYTES>>>(h0, b2, out);
}

// round 16
// speedup vs baseline: 1.1210x; 1.0415x over previous
#include <cuda_runtime.h>
#include <cuda_fp16.h>
#include <math.h>
#include <stdint.h>

#define N_NODES 50000
#define N_EDGES 800000
#define NFEAT   512
#define NHID    128
#define NCLASS  64

// Scratch (allocation-free) — h0/h1 fp16
__device__ uint16_t g_h0[(size_t)N_NODES * NHID];
__device__ uint16_t g_h1[(size_t)N_NODES * NHID];
__device__ uint16_t g_w1t_hi[NHID * NFEAT];   // W1^T hi fp16 [n][k]
__device__ uint16_t g_w1t_lo[NHID * NFEAT];   // W1^T lo fp16 [n][k]
__device__ uint16_t g_w2t_hi[NCLASS * NHID];  // W2^T hi fp16 [n][k]
__device__ uint16_t g_w2t_lo[NCLASS * NHID];  // W2^T lo fp16 [n][k]
__device__ int g_rowptr[N_NODES + 1];

// ---------------------------------------------------------------------------
// helpers
// ---------------------------------------------------------------------------
__device__ __forceinline__ uint32_t smem_u32(const void* p) {
    uint32_t a;
    asm("{ .reg .u64 t; cvta.to.shared.u64 t, %1; cvt.u32.u64 %0, t; }" : "=r"(a) : "l"(p));
    return a;
}
__device__ __forceinline__ uint32_t pack_f16x2(float lo, float hi) {
    uint32_t r;
    asm("cvt.rn.f16x2.f32 %0, %1, %2;" : "=r"(r) : "f"(hi), "f"(lo));
    return r;
}
__device__ __forceinline__ float f16_lo_f32(uint32_t p) {
    float f; asm("{ .reg .f16 h; mov.b32 {h, _}, %1; cvt.f32.f16 %0, h; }" : "=f"(f) : "r"(p));
    return f;
}
__device__ __forceinline__ float f16_hi_f32(uint32_t p) {
    float f; asm("{ .reg .f16 h; mov.b32 {_, h}, %1; cvt.f32.f16 %0, h; }" : "=f"(f) : "r"(p));
    return f;
}

__device__ __forceinline__ void mma_f16(float* d, const uint32_t* a,
                                        uint32_t b0, uint32_t b1) {
    asm("mma.sync.aligned.m16n8k16.row.col.f32.f16.f16.f32 "
        "{%0,%1,%2,%3}, {%4,%5,%6,%7}, {%8,%9}, {%0,%1,%2,%3};"
        : "+f"(d[0]), "+f"(d[1]), "+f"(d[2]), "+f"(d[3])
        : "r"(a[0]), "r"(a[1]), "r"(a[2]), "r"(a[3]), "r"(b0), "r"(b1));
}
#define LDSM4(r0, r1, r2, r3, addr) \
    asm volatile("ldmatrix.sync.aligned.m8n8.x4.shared.b16 {%0,%1,%2,%3}, [%4];" \
        : "=r"(r0), "=r"(r1), "=r"(r2), "=r"(r3) : "r"(addr))

__device__ __forceinline__ void cp_async16(uint32_t dst, const void* src) {
    asm volatile("cp.async.cg.shared.global [%0], [%1], 16;" :: "r"(dst), "l"(src));
}
#define CP_COMMIT() asm volatile("cp.async.commit_group;" ::: "memory")
#define CP_WAIT0()  asm volatile("cp.async.wait_group 0;" ::: "memory")
#define CP_WAIT2()  asm volatile("cp.async.wait_group 2;" ::: "memory")
#define CP_WAIT3()  asm volatile("cp.async.wait_group 3;" ::: "memory")

// ---------------------------------------------------------------------------
// merged prep kernel: [0,128) W1, [128,144) W2, [144, 144+3125) rowptr
// ---------------------------------------------------------------------------
#define PREP_W1_BLOCKS 128
#define PREP_W2_BLOCKS 16
#define PREP_RP_BLOCKS ((N_EDGES + 255) / 256)
#define PREP_BLOCKS (PREP_W1_BLOCKS + PREP_W2_BLOCKS + PREP_RP_BLOCKS)

__global__ void prep_all_kernel(const float* __restrict__ W1,
                                const float* __restrict__ W2,
                                const int* __restrict__ rows)
{
    const int b = blockIdx.x;
    if (b < PREP_W1_BLOCKS) {
        int idx = b * 256 + threadIdx.x;
        if (idx >= NHID * NFEAT / 2) return;
        int n = idx >> 8;
        int k2 = (idx & 255) * 2;
        float w0 = W1[(size_t)k2 * NHID + n];
        float w1 = W1[(size_t)(k2 + 1) * NHID + n];
        uint32_t ph = pack_f16x2(w0, w1);
        uint32_t pl = pack_f16x2(w0 - f16_lo_f32(ph), w1 - f16_hi_f32(ph));
        *(uint32_t*)&g_w1t_hi[n * NFEAT + k2] = ph;
        *(uint32_t*)&g_w1t_lo[n * NFEAT + k2] = pl;
    } else if (b < PREP_W1_BLOCKS + PREP_W2_BLOCKS) {
        int idx = (b - PREP_W1_BLOCKS) * 256 + threadIdx.x;
        if (idx >= NCLASS * NHID / 2) return;
        int n = idx >> 6;
        int k2 = (idx & 63) * 2;
        float w0 = W2[(size_t)k2 * NCLASS + n];
        float w1 = W2[(size_t)(k2 + 1) * NCLASS + n];
        uint32_t ph = pack_f16x2(w0, w1);
        uint32_t pl = pack_f16x2(w0 - f16_lo_f32(ph), w1 - f16_hi_f32(ph));
        *(uint32_t*)&g_w2t_hi[n * NHID + k2] = ph;
        *(uint32_t*)&g_w2t_lo[n * NHID + k2] = pl;
    } else {
        int e = (b - PREP_W1_BLOCKS - PREP_W2_BLOCKS) * 256 + threadIdx.x;
        if (e >= N_EDGES) return;
        int r = rows[e];
        int rp = (e == 0) ? -1 : rows[e - 1];
        for (int q = rp + 1; q <= r; ++q) g_rowptr[q] = e;
        if (e == N_EDGES - 1)
            for (int q = r + 1; q <= N_NODES; ++q) g_rowptr[q] = N_EDGES;
    }
}

// ---------------------------------------------------------------------------
// GEMM1: fp16 2-term, depth-2 async pipeline, ldmatrix, 512 threads.
// CTA 128x128, 16 warps (8M x 2N), warp tile 16x64, BK=32.  (R13, kept)
// ---------------------------------------------------------------------------
#define LDA   40
#define AF16  0
#define BBUF(b) (5120 + (b) * 10240)
#define FP16_ELEMS 25600
#define LDAF  36
#define STAGF 4608
#define SMEM_G1_BYTES (FP16_ELEMS * 2 + 3 * STAGF * 4)   // 106496

__global__ __launch_bounds__(512, 2) void gemm1_mma_kernel(const float* __restrict__ x,
                                                           uint16_t* __restrict__ out)
{
    extern __shared__ uint16_t sm[];
    float* stag = (float*)(sm + FP16_ELEMS);
    const uint32_t smb = smem_u32(sm);
    const uint32_t stb = smem_u32(stag);

    const int tid  = threadIdx.x;
    const int wid  = tid >> 5;        // 0..15
    const int lane = tid & 31;
    const int m0   = blockIdx.x * 128;
    const int wm = (wid >> 1) * 16;   // 0..112
    const int wn = (wid & 1) * 64;    // 0,64

    float acc[8][4];
#pragma unroll
    for (int j = 0; j < 8; j++)
#pragma unroll
        for (int q = 0; q < 4; q++) acc[j][q] = 0.f;

    const int arow = tid >> 2;        // 0..127
    const int aq   = tid & 3;         // 0..3
    int rg = m0 + arow;
    if (rg >= N_NODES) rg = N_NODES - 1;
    const float* xrow = x + (size_t)rg * NFEAT + aq * 8;
    const uint16_t* bhrow = g_w1t_hi + (size_t)arow * NFEAT + aq * 8;
    const uint16_t* blrow = g_w1t_lo + (size_t)arow * NFEAT + aq * 8;
    const int stA  = arow * LDAF + aq * 8;
    const int dstA = AF16 + arow * LDA + aq * 8;
    const int dstB = arow * LDA + aq * 8;

    const int lrow = (lane & 7) + ((lane >> 3) & 1) * 8;
    const int lkof = (lane >> 4) * 8;
    const uint32_t aAddr0 = smb + (uint32_t)((AF16 + (wm + lrow) * LDA + lkof) * 2);
    const uint32_t bRel   = (uint32_t)(((wn + lrow) * LDA + lkof) * 2);

#define COPY_A(c, st) do {                                                    \
        uint32_t da = stb + ((st) * STAGF + stA) * 4;                         \
        cp_async16(da,      xrow + (c) * 32);                                 \
        cp_async16(da + 16, xrow + (c) * 32 + 4);                             \
        CP_COMMIT();                                                          \
    } while (0)

#define COPY_B(c, buf) do {                                                   \
        uint32_t dh = smb + (BBUF(buf) + dstB) * 2;                           \
        uint32_t dl = dh + 5120 * 2;                                          \
        cp_async16(dh, bhrow + (c) * 32);                                     \
        cp_async16(dl, blrow + (c) * 32);                                     \
        CP_COMMIT();                                                          \
    } while (0)

#define CONV_A(st) do {                                                       \
        const float* sf = stag + (st) * STAGF + stA;                          \
        float4 v0 = *(const float4*)(sf);                                     \
        float4 v1 = *(const float4*)(sf + 4);                                 \
        uint32_t H[4];                                                        \
        H[0] = pack_f16x2(v0.x, v0.y); H[1] = pack_f16x2(v0.z, v0.w);         \
        H[2] = pack_f16x2(v1.x, v1.y); H[3] = pack_f16x2(v1.z, v1.w);         \
        *(uint4*)(sm + dstA) = *(uint4*)&H[0];                                \
    } while (0)

    COPY_A(0, 0);
    COPY_B(0, 0);
    COPY_A(1, 1);
    COPY_B(1, 1);

#pragma unroll 1
    for (int c = 0; c < 16; ++c) {
        if (c < 14) COPY_A(c + 2, (c + 2) % 3);

        if (c < 14)       CP_WAIT3();
        else if (c == 14) CP_WAIT2();
        else              CP_WAIT0();

        CONV_A(c % 3);
        __syncthreads();

        const uint32_t bHi = smb + (uint32_t)(BBUF(c & 1) * 2) + bRel;
        const uint32_t bLo = bHi + 5120 * 2;
#pragma unroll
        for (int ks = 0; ks < 2; ++ks) {
            const uint32_t kb = ks * 32;
            uint32_t a0[4];
            LDSM4(a0[0], a0[1], a0[2], a0[3], aAddr0 + kb);
#pragma unroll
            for (int ntp = 0; ntp < 4; ++ntp) {
                const uint32_t boff = (uint32_t)(ntp * 16 * LDA * 2) + kb;
                uint32_t bh[4], bl[4];
                LDSM4(bh[0], bh[1], bh[2], bh[3], bHi + boff);
                LDSM4(bl[0], bl[1], bl[2], bl[3], bLo + boff);
                float* c0 = acc[ntp * 2];
                float* c1 = acc[ntp * 2 + 1];
                mma_f16(c0, a0, bh[0], bh[2]);
                mma_f16(c1, a0, bh[1], bh[3]);
                mma_f16(c0, a0, bl[0], bl[2]);
                mma_f16(c1, a0, bl[1], bl[3]);
            }
        }
        __syncthreads();

        if (c < 14) COPY_B(c + 2, c & 1);
    }

    // epilogue: fp16 output
    {
        int r0 = m0 + wm + (lane >> 2);
        int r1 = r0 + 8;
#pragma unroll
        for (int nt = 0; nt < 8; ++nt) {
            int cc = wn + nt * 8 + (lane & 3) * 2;
            if (r0 < N_NODES)
                *(uint32_t*)(out + (size_t)r0 * NHID + cc) =
                    pack_f16x2(acc[nt][0], acc[nt][1]);
            if (r1 < N_NODES)
                *(uint32_t*)(out + (size_t)r1 * NHID + cc) =
                    pack_f16x2(acc[nt][2], acc[nt][3]);
        }
    }
}

// ---------------------------------------------------------------------------
// SpMM: warp per row, row_ptr, 4-edge unroll, fp16 h. (R12 measured-best)
// ---------------------------------------------------------------------------
template <bool RELU>
__global__ __launch_bounds__(256) void spmm_kernel(const int* __restrict__ cols,
                                                   const float* __restrict__ vals,
                                                   const uint16_t* __restrict__ hin,
                                                   const float* __restrict__ bias,
                                                   uint16_t* __restrict__ hout)
{
    const int gw   = (blockIdx.x * blockDim.x + threadIdx.x) >> 5;
    const int lane = threadIdx.x & 31;
    if (gw >= N_NODES) return;

    const int start = g_rowptr[gw];
    const int end   = g_rowptr[gw + 1];

    float ax = 0.f, ay = 0.f, az = 0.f, aw = 0.f;
    int e = start;
    for (; e + 4 <= end; e += 4) {
        int   c0 = cols[e],     c1 = cols[e + 1], c2 = cols[e + 2], c3 = cols[e + 3];
        float v0 = vals[e],     v1 = vals[e + 1], v2 = vals[e + 2], v3 = vals[e + 3];
        uint2 p0 = *(const uint2*)(hin + (size_t)c0 * NHID + lane * 4);
        uint2 p1 = *(const uint2*)(hin + (size_t)c1 * NHID + lane * 4);
        uint2 p2 = *(const uint2*)(hin + (size_t)c2 * NHID + lane * 4);
        uint2 p3 = *(const uint2*)(hin + (size_t)c3 * NHID + lane * 4);
        float2 f;
        f = __half22float2(*(__half2*)&p0.x); ax = fmaf(v0, f.x, ax); ay = fmaf(v0, f.y, ay);
        f = __half22float2(*(__half2*)&p0.y); az = fmaf(v0, f.x, az); aw = fmaf(v0, f.y, aw);
        f = __half22float2(*(__half2*)&p1.x); ax = fmaf(v1, f.x, ax); ay = fmaf(v1, f.y, ay);
        f = __half22float2(*(__half2*)&p1.y); az = fmaf(v1, f.x, az); aw = fmaf(v1, f.y, aw);
        f = __half22float2(*(__half2*)&p2.x); ax = fmaf(v2, f.x, ax); ay = fmaf(v2, f.y, ay);
        f = __half22float2(*(__half2*)&p2.y); az = fmaf(v2, f.x, az); aw = fmaf(v2, f.y, aw);
        f = __half22float2(*(__half2*)&p3.x); ax = fmaf(v3, f.x, ax); ay = fmaf(v3, f.y, ay);
        f = __half22float2(*(__half2*)&p3.y); az = fmaf(v3, f.x, az); aw = fmaf(v3, f.y, aw);
    }
    for (; e < end; ++e) {
        int   c0 = cols[e];
        float v0 = vals[e];
        uint2 p0 = *(const uint2*)(hin + (size_t)c0 * NHID + lane * 4);
        float2 f;
        f = __half22float2(*(__half2*)&p0.x); ax = fmaf(v0, f.x, ax); ay = fmaf(v0, f.y, ay);
        f = __half22float2(*(__half2*)&p0.y); az = fmaf(v0, f.x, az); aw = fmaf(v0, f.y, aw);
    }
    if (RELU) {
        float4 b = ((const float4*)bias)[lane];
        ax = fmaxf(ax + b.x, 0.f); ay = fmaxf(ay + b.y, 0.f);
        az = fmaxf(az + b.z, 0.f); aw = fmaxf(aw + b.w, 0.f);
    }
    uint2 st;
    st.x = pack_f16x2(ax, ay);
    st.y = pack_f16x2(az, aw);
    *(uint2*)(hout + (size_t)gw * NHID + lane * 4) = st;
}

// ---------------------------------------------------------------------------
// GEMM2: fp16 2-term + fused bias + log_softmax. (kept)
// ---------------------------------------------------------------------------
#define LDH 136
#define G2_A  0
#define G2_WH 8704
#define G2_WL 17408
#define SMEM_G2_BYTES (26112 * 2)   // 52224

__global__ __launch_bounds__(128) void gemm2_mma_kernel(const uint16_t* __restrict__ h,
                                                        const float* __restrict__ b2,
                                                        float* __restrict__ out)
{
    extern __shared__ uint16_t s2[];

    const int tid  = threadIdx.x;
    const int lane = tid & 31;
    const int wid  = tid >> 5;
    const int r0   = blockIdx.x * 64;

    const int row = tid >> 1, half = tid & 1;
    int rg = r0 + row;
    if (rg >= N_NODES) rg = N_NODES - 1;

    {
        const uint16_t* hp = h + (size_t)rg * NHID + half * 64;
        uint16_t* dp = s2 + G2_A + row * LDH + half * 64;
#pragma unroll
        for (int j = 0; j < 8; ++j)
            *(uint4*)(dp + j * 8) = *(const uint4*)(hp + j * 8);
    }
    {
        const int n = row;
        const uint16_t* wh = g_w2t_hi + n * NHID + half * 64;
        const uint16_t* wl = g_w2t_lo + n * NHID + half * 64;
        uint16_t* dh = s2 + G2_WH + n * LDH + half * 64;
        uint16_t* dl = s2 + G2_WL + n * LDH + half * 64;
#pragma unroll
        for (int j = 0; j < 8; ++j) {
            *(uint4*)(dh + j * 8) = *(const uint4*)(wh + j * 8);
            *(uint4*)(dl + j * 8) = *(const uint4*)(wl + j * 8);
        }
    }
    __syncthreads();

    float acc[8][4];
#pragma unroll
    for (int nt = 0; nt < 8; ++nt)
#pragma unroll
        for (int q = 0; q < 4; ++q) acc[nt][q] = 0.f;

    const int wr = wid * 16;
#pragma unroll
    for (int ks = 0; ks < 8; ++ks) {
        const int kk = ks * 16;
        const int r  = wr + (lane >> 2);
        const int cc = kk + (lane & 3) * 2;
        uint32_t a[4];
        a[0] = *(const uint32_t*)(s2 + G2_A + r * LDH + cc);
        a[1] = *(const uint32_t*)(s2 + G2_A + (r + 8) * LDH + cc);
        a[2] = *(const uint32_t*)(s2 + G2_A + r * LDH + cc + 8);
        a[3] = *(const uint32_t*)(s2 + G2_A + (r + 8) * LDH + cc + 8);
#pragma unroll
        for (int nt = 0; nt < 8; ++nt) {
            int n  = nt * 8 + (lane >> 2);
            int kq = kk + (lane & 3) * 2;
            uint32_t bh0 = *(const uint32_t*)(s2 + G2_WH + n * LDH + kq);
            uint32_t bh1 = *(const uint32_t*)(s2 + G2_WH + n * LDH + kq + 8);
            uint32_t bl0 = *(const uint32_t*)(s2 + G2_WL + n * LDH + kq);
            uint32_t bl1 = *(const uint32_t*)(s2 + G2_WL + n * LDH + kq + 8);
            mma_f16(acc[nt], a, bh0, bh1);
            mma_f16(acc[nt], a, bl0, bl1);
        }
    }

#pragma unroll
    for (int nt = 0; nt < 8; ++nt) {
        int c = nt * 8 + (lane & 3) * 2;
        float bb0 = b2[c], bb1 = b2[c + 1];
        acc[nt][0] += bb0; acc[nt][1] += bb1;
        acc[nt][2] += bb0; acc[nt][3] += bb1;
    }

    float m0 = -1e30f, m1 = -1e30f;
#pragma unroll
    for (int nt = 0; nt < 8; ++nt) {
        m0 = fmaxf(m0, fmaxf(acc[nt][0], acc[nt][1]));
        m1 = fmaxf(m1, fmaxf(acc[nt][2], acc[nt][3]));
    }
    m0 = fmaxf(m0, __shfl_xor_sync(0xffffffffu, m0, 1));
    m0 = fmaxf(m0, __shfl_xor_sync(0xffffffffu, m0, 2));
    m1 = fmaxf(m1, __shfl_xor_sync(0xffffffffu, m1, 1));
    m1 = fmaxf(m1, __shfl_xor_sync(0xffffffffu, m1, 2));

    float s0 = 0.f, s1 = 0.f;
#pragma unroll
    for (int nt = 0; nt < 8; ++nt) {
        s0 += expf(acc[nt][0] - m0) + expf(acc[nt][1] - m0);
        s1 += expf(acc[nt][2] - m1) + expf(acc[nt][3] - m1);
    }
    s0 += __shfl_xor_sync(0xffffffffu, s0, 1);
    s0 += __shfl_xor_sync(0xffffffffu, s0, 2);
    s1 += __shfl_xor_sync(0xffffffffu, s1, 1);
    s1 += __shfl_xor_sync(0xffffffffu, s1, 2);
    const float lse0 = m0 + logf(s0);
    const float lse1 = m1 + logf(s1);

    const int row0 = r0 + wr + (lane >> 2);
    const int row1 = row0 + 8;
#pragma unroll
    for (int nt = 0; nt < 8; ++nt) {
        int c = nt * 8 + (lane & 3) * 2;
        if (row0 < N_NODES)
            *(float2*)(out + (size_t)row0 * NCLASS + c) =
                make_float2(acc[nt][0] - lse0, acc[nt][1] - lse0);
        if (row1 < N_NODES)
            *(float2*)(out + (size_t)row1 * NCLASS + c) =
                make_float2(acc[nt][2] - lse1, acc[nt][3] - lse1);
    }
}

// ---------------------------------------------------------------------------
extern "C" void kernel_launch(void* const* d_in, const int* in_sizes, int n_in,
                              void* d_out, int out_size)
{
    const float* x    = (const float*)d_in[0];
    const int*   rows = (const int*)  d_in[1];
    const int*   cols = (const int*)  d_in[2];
    const float* vals = (const float*)d_in[3];
    const float* W1   = (const float*)d_in[4];
    const float* b1   = (const float*)d_in[5];
    const float* W2   = (const float*)d_in[6];
    const float* b2   = (const float*)d_in[7];
    float* out = (float*)d_out;

    uint16_t *h0, *h1;
    cudaGetSymbolAddress((void**)&h0, g_h0);
    cudaGetSymbolAddress((void**)&h1, g_h1);

    cudaFuncSetAttribute(gemm1_mma_kernel, cudaFuncAttributeMaxDynamicSharedMemorySize, SMEM_G1_BYTES);
    cudaFuncSetAttribute(gemm2_mma_kernel, cudaFuncAttributeMaxDynamicSharedMemorySize, SMEM_G2_BYTES);

    // 0) merged prep: W1^T, W2^T hi/lo + row_ptr in one launch
    prep_all_kernel<<<PREP_BLOCKS, 256>>>(W1, W2, rows);

    // 1) h0 = X @ W1  (R13 fused pipeline)
    gemm1_mma_kernel<<<(N_NODES + 127) / 128, 512, SMEM_G1_BYTES>>>(x, h0);

    // 2) h1 = relu(A @ h0 + b1)   (R12 spmm)
    const int spmm_blocks = (N_NODES * 32 + 255) / 256;
    spmm_kernel<true><<<spmm_blocks, 256>>>(cols, vals, h0, b1, h1);

    // 3) h0 <- A @ h1
    spmm_kernel<false><<<spmm_blocks, 256>>>(cols, vals, h1, b1, h0);

    // 4) out = logsoftmax(h0 @ W2 + b2)
    gemm2_mma_kernel<<<(N_NODES + 63) / 64, 128, SMEM_G2_BYTES>>>(h0, b2, out);
}